// round 17
// baseline (speedup 1.0000x reference)
#include <cuda_runtime.h>
#include <math.h>

// ---------------- problem constants ----------------
#define B_  2
#define S_  4096
#define D_  768
#define H_  12
#define DH_ 64
#define L_  2
#define F_  3072
#define C_  256
#define M_  (B_*S_)
#define NEGV (-1000000000.0f)
#define GNS 32            // global-attn split chunks
#define GCK 128           // keys per chunk

// ---------------- scratch ----------------
__device__ float g_h  [M_ * D_];
__device__ float g_q  [M_ * D_];
__device__ float g_k  [M_ * D_];
__device__ float g_v  [M_ * D_];
__device__ float g_ctx[M_ * D_];
__device__ float g_t  [M_ * D_];
__device__ float g_f  [M_ * F_];
__device__ float g_gp [B_ * H_ * GNS * 66];   // per-chunk partials: 64 o + m + s

// ---------------- helpers ----------------
__device__ __forceinline__ float warp_sum(float v) {
    #pragma unroll
    for (int o = 16; o; o >>= 1) v += __shfl_xor_sync(0xffffffffu, v, o);
    return v;
}
__device__ __forceinline__ float warp_max(float v) {
    #pragma unroll
    for (int o = 16; o; o >>= 1) v = fmaxf(v, __shfl_xor_sync(0xffffffffu, v, o));
    return v;
}
__device__ float block_sum(float v, float* red) {
    int lane = threadIdx.x & 31, w = threadIdx.x >> 5;
    v = warp_sum(v);
    __syncthreads();
    if (lane == 0) red[w] = v;
    __syncthreads();
    int nw = (blockDim.x + 31) >> 5;
    float r = (threadIdx.x < nw) ? red[threadIdx.x] : 0.0f;
    if (w == 0) { r = warp_sum(r); if (lane == 0) red[0] = r; }
    __syncthreads();
    return red[0];
}
__device__ float block_max(float v, float* red) {
    int lane = threadIdx.x & 31, w = threadIdx.x >> 5;
    v = warp_max(v);
    __syncthreads();
    if (lane == 0) red[w] = v;
    __syncthreads();
    int nw = (blockDim.x + 31) >> 5;
    float r = (threadIdx.x < nw) ? red[threadIdx.x] : -INFINITY;
    if (w == 0) { r = warp_max(r); if (lane == 0) red[0] = r; }
    __syncthreads();
    return red[0];
}

__device__ __forceinline__ unsigned f2tf(float v) {
    unsigned r; asm("cvt.rna.tf32.f32 %0, %1;" : "=r"(r) : "f"(v)); return r;
}
__device__ __forceinline__ void mma_tf32(float* c, const unsigned* a, const unsigned* b) {
    asm volatile(
        "mma.sync.aligned.m16n8k8.row.col.f32.tf32.tf32.f32 "
        "{%0,%1,%2,%3},{%4,%5,%6,%7},{%8,%9},{%0,%1,%2,%3};\n"
        : "+f"(c[0]), "+f"(c[1]), "+f"(c[2]), "+f"(c[3])
        : "r"(a[0]), "r"(a[1]), "r"(a[2]), "r"(a[3]), "r"(b[0]), "r"(b[1]));
}
// cp.async with zero-fill: src_bytes < 16 zero-fills the remainder
__device__ __forceinline__ void cp_async16z(unsigned smem, const void* g, int src_bytes) {
    asm volatile("cp.async.ca.shared.global [%0], [%1], 16, %2;\n"
                 :: "r"(smem), "l"(g), "r"(src_bytes));
}

// ---------------- embedding + layernorm ----------------
__global__ void embed_ln_kernel(const int* __restrict__ ids,
                                const float* __restrict__ tok,
                                const float* __restrict__ pos,
                                const float* __restrict__ g,
                                const float* __restrict__ be,
                                float* __restrict__ out) {
    __shared__ float red[32];
    int row = blockIdx.x;
    int s = row % S_;
    int id = ids[row];
    const float* tp = tok + (size_t)id * D_;
    const float* pp = pos + (size_t)s  * D_;
    float vals[3]; float lsum = 0.0f;
    #pragma unroll
    for (int i = 0; i < 3; i++) {
        int c = threadIdx.x + i * 256;
        vals[i] = tp[c] + pp[c];
        lsum += vals[i];
    }
    float mean = block_sum(lsum, red) * (1.0f / D_);
    float lv = 0.0f;
    #pragma unroll
    for (int i = 0; i < 3; i++) { float d = vals[i] - mean; lv += d * d; }
    float var = block_sum(lv, red) * (1.0f / D_);
    float inv = rsqrtf(var + 1e-5f);
    float* op = out + (size_t)row * D_;
    #pragma unroll
    for (int i = 0; i < 3; i++) {
        int c = threadIdx.x + i * 256;
        op[c] = (vals[i] - mean) * inv * g[c] + be[c];
    }
}

// ---------------- residual add + layernorm ----------------
__global__ void add_ln_kernel(const float* __restrict__ x,
                              const float* __restrict__ r,
                              const float* __restrict__ g,
                              const float* __restrict__ be,
                              float* __restrict__ out) {
    __shared__ float red[32];
    int row = blockIdx.x;
    const float* xp = x + (size_t)row * D_;
    const float* rp = r + (size_t)row * D_;
    float vals[3]; float lsum = 0.0f;
    #pragma unroll
    for (int i = 0; i < 3; i++) {
        int c = threadIdx.x + i * 256;
        vals[i] = xp[c] + rp[c];
        lsum += vals[i];
    }
    float mean = block_sum(lsum, red) * (1.0f / D_);
    float lv = 0.0f;
    #pragma unroll
    for (int i = 0; i < 3; i++) { float d = vals[i] - mean; lv += d * d; }
    float var = block_sum(lv, red) * (1.0f / D_);
    float inv = rsqrtf(var + 1e-5f);
    float* op = out + (size_t)row * D_;
    #pragma unroll
    for (int i = 0; i < 3; i++) {
        int c = threadIdx.x + i * 256;
        op[c] = (vals[i] - mean) * inv * g[c] + be[c];
    }
}

// ---------------- tf32 mma GEMM (R3 layout; cvt at smem store) — FROZEN ----------------
#define TBM 128
#define TBN 128
#define TBK 16
#define ASTR 20
#define BSTR 132

__global__ __launch_bounds__(256) void gemm_tf32_kernel(
        const float* __restrict__ A,
        const float* __restrict__ W0, const float* __restrict__ W1p,
        const float* __restrict__ W2p,
        const float* __restrict__ bi0, const float* __restrict__ bi1,
        const float* __restrict__ bi2,
        float* __restrict__ C0, float* __restrict__ C1, float* __restrict__ C2,
        int M, int N, int K, int act, float s0, float s1, float s2) {
    __shared__ unsigned As[2][TBM * ASTR];
    __shared__ unsigned Bs[2][TBK * BSTR];

    int z = blockIdx.z;
    const float* W    = (z == 0) ? W0  : (z == 1) ? W1p : W2p;
    const float* bias = (z == 0) ? bi0 : (z == 1) ? bi1 : bi2;
    float*       Co   = (z == 0) ? C0  : (z == 1) ? C1  : C2;
    float scale       = (z == 0) ? s0  : (z == 1) ? s1  : s2;

    int tid = threadIdx.x;
    int lane = tid & 31, wid = tid >> 5;
    int wm = (wid & 3) * 32;
    int wn = (wid >> 2) * 64;
    int gid = lane >> 2, tig = lane & 3;
    size_t rowBase = (size_t)blockIdx.y * TBM;
    size_t colBase = (size_t)blockIdx.x * TBN;

    int s0i = tid, s1i = tid + 256;
    int ar0 = s0i >> 2, ac0 = (s0i & 3) * 4;
    int ar1 = s1i >> 2, ac1 = (s1i & 3) * 4;
    int br0 = s0i >> 5, bc0 = (s0i & 31) * 4;
    int br1 = s1i >> 5, bc1 = (s1i & 31) * 4;

    float c[2][8][4];
    #pragma unroll
    for (int mi = 0; mi < 2; mi++)
        #pragma unroll
        for (int ni = 0; ni < 8; ni++)
            #pragma unroll
            for (int q = 0; q < 4; q++) c[mi][ni][q] = 0.0f;

    int ntiles = K / TBK;

    float4 aPre0, aPre1, bPre0, bPre1;
    aPre0 = *(const float4*)&A[(rowBase + ar0) * K + ac0];
    aPre1 = *(const float4*)&A[(rowBase + ar1) * K + ac1];
    bPre0 = *(const float4*)&W[(size_t)br0 * N + colBase + bc0];
    bPre1 = *(const float4*)&W[(size_t)br1 * N + colBase + bc1];
    {
        unsigned* p;
        p = &As[0][ar0 * ASTR + ac0];
        p[0]=f2tf(aPre0.x); p[1]=f2tf(aPre0.y); p[2]=f2tf(aPre0.z); p[3]=f2tf(aPre0.w);
        p = &As[0][ar1 * ASTR + ac1];
        p[0]=f2tf(aPre1.x); p[1]=f2tf(aPre1.y); p[2]=f2tf(aPre1.z); p[3]=f2tf(aPre1.w);
        p = &Bs[0][br0 * BSTR + bc0];
        p[0]=f2tf(bPre0.x); p[1]=f2tf(bPre0.y); p[2]=f2tf(bPre0.z); p[3]=f2tf(bPre0.w);
        p = &Bs[0][br1 * BSTR + bc1];
        p[0]=f2tf(bPre1.x); p[1]=f2tf(bPre1.y); p[2]=f2tf(bPre1.z); p[3]=f2tf(bPre1.w);
    }
    __syncthreads();

    for (int kt = 0; kt < ntiles; kt++) {
        int cur = kt & 1;
        bool hasNext = (kt + 1) < ntiles;
        if (hasNext) {
            int k0 = (kt + 1) * TBK;
            aPre0 = *(const float4*)&A[(rowBase + ar0) * K + k0 + ac0];
            aPre1 = *(const float4*)&A[(rowBase + ar1) * K + k0 + ac1];
            bPre0 = *(const float4*)&W[(size_t)(k0 + br0) * N + colBase + bc0];
            bPre1 = *(const float4*)&W[(size_t)(k0 + br1) * N + colBase + bc1];
        }

        #pragma unroll
        for (int ks = 0; ks < 2; ks++) {
            int kb = ks * 8;
            unsigned af[2][4];
            #pragma unroll
            for (int mi = 0; mi < 2; mi++) {
                const unsigned* ap = &As[cur][(wm + mi * 16 + gid) * ASTR + kb + tig];
                af[mi][0] = ap[0];
                af[mi][1] = ap[8 * ASTR];
                af[mi][2] = ap[4];
                af[mi][3] = ap[8 * ASTR + 4];
            }
            unsigned bf[8][2];
            #pragma unroll
            for (int ni = 0; ni < 8; ni++) {
                const unsigned* bp = &Bs[cur][(kb + tig) * BSTR + wn + ni * 8 + gid];
                bf[ni][0] = bp[0];
                bf[ni][1] = bp[4 * BSTR];
            }
            #pragma unroll
            for (int mi = 0; mi < 2; mi++)
                #pragma unroll
                for (int ni = 0; ni < 8; ni++)
                    mma_tf32(c[mi][ni], af[mi], bf[ni]);
        }

        if (hasNext) {
            int nb = cur ^ 1;
            unsigned* p;
            p = &As[nb][ar0 * ASTR + ac0];
            p[0]=f2tf(aPre0.x); p[1]=f2tf(aPre0.y); p[2]=f2tf(aPre0.z); p[3]=f2tf(aPre0.w);
            p = &As[nb][ar1 * ASTR + ac1];
            p[0]=f2tf(aPre1.x); p[1]=f2tf(aPre1.y); p[2]=f2tf(aPre1.z); p[3]=f2tf(aPre1.w);
            p = &Bs[nb][br0 * BSTR + bc0];
            p[0]=f2tf(bPre0.x); p[1]=f2tf(bPre0.y); p[2]=f2tf(bPre0.z); p[3]=f2tf(bPre0.w);
            p = &Bs[nb][br1 * BSTR + bc1];
            p[0]=f2tf(bPre1.x); p[1]=f2tf(bPre1.y); p[2]=f2tf(bPre1.z); p[3]=f2tf(bPre1.w);
            __syncthreads();
        }
    }

    #pragma unroll
    for (int mi = 0; mi < 2; mi++) {
        size_t r0 = rowBase + wm + mi * 16 + gid;
        size_t r1 = r0 + 8;
        #pragma unroll
        for (int ni = 0; ni < 8; ni++) {
            size_t col = colBase + wn + ni * 8 + tig * 2;
            float b0 = bias[col], b1 = bias[col + 1];
            float v0 = (c[mi][ni][0] + b0) * scale;
            float v1 = (c[mi][ni][1] + b1) * scale;
            float v2 = (c[mi][ni][2] + b0) * scale;
            float v3 = (c[mi][ni][3] + b1) * scale;
            if (act == 1) {
                v0 = 0.5f * v0 * (1.0f + erff(v0 * 0.70710678f));
                v1 = 0.5f * v1 * (1.0f + erff(v1 * 0.70710678f));
                v2 = 0.5f * v2 * (1.0f + erff(v2 * 0.70710678f));
                v3 = 0.5f * v3 * (1.0f + erff(v3 * 0.70710678f));
            }
            *(float2*)&Co[r0 * N + col] = make_float2(v0, v1);
            *(float2*)&Co[r1 * N + col] = make_float2(v2, v3);
        }
    }
}

// ---------------- sliding-window attention: single-pass flash-style ----------------
// 16-query tiles; per 64-key tile: stage K+V, score mma, online softmax via small
// P buffer (16x68), PV mma with accumulator rescale. smem 44KB -> 4 CTAs/SM.
#define AT_Q   0
#define AT_K   1088
#define AT_V   5440
#define AT_P   10048
#define AT_G   11136
#define AT_M   11152
#define AT_S   11168
#define AT_R   11184
#define AT_MV  11200
#define AT_SMEM (11264 * 4)

__global__ __launch_bounds__(256, 4) void sw_attn_kernel(
        const float* __restrict__ q,
        const float* __restrict__ k,
        const float* __restrict__ v,
        const int* __restrict__ mask,
        float* __restrict__ ctx) {
    extern __shared__ float sm[];
    float* qS  = sm + AT_Q;    // [16][68]
    float* Ks  = sm + AT_K;    // [64][68] raw K
    float* Vs  = sm + AT_V;    // [64][72] raw V
    float* P   = sm + AT_P;    // [16][68] probs
    float* gsc = sm + AT_G;
    float* mrun= sm + AT_M;
    float* srun= sm + AT_S;
    float* rsc = sm + AT_R;
    float* mv  = sm + AT_MV;
    unsigned* Pu = (unsigned*)P;

    int tid = threadIdx.x;
    int lane = tid & 31, w = tid >> 5;
    int gid = lane >> 2, ti = lane & 3;
    int h = blockIdx.y, b = blockIdx.z;
    int qbase = blockIdx.x * 16;
    int n = qbase / C_;
    int cbase = qbase % C_;
    int j0 = (n - 1) * C_;
    int n0 = w * 8;

    int ktlo = cbase >> 6;
    int kthi = (cbase + 2 * C_ + 15) >> 6;

    // stage q raw [q][d], stride 68
    {
        int r = tid >> 4, c4 = (tid & 15) * 4;
        *(float4*)&qS[r * 68 + c4] =
            *(const float4*)&q[((size_t)(b * S_ + qbase + r)) * D_ + h * DH_ + c4];
    }
    if (tid < 16) { mrun[tid] = -INFINITY; srun[tid] = 0.0f; }
    __syncthreads();

    // global-token score (16 rows)
    if (tid < 16) {
        float acc = 0.0f;
        const float* k0p = k + ((size_t)(b * S_)) * D_ + h * DH_;
        #pragma unroll 8
        for (int d = 0; d < 64; d++)
            acc = fmaf(qS[tid * 68 + d], k0p[d], acc);
        gsc[tid] = (mask[b * S_] > 0) ? acc : NEGV;
    }

    // hoist Q fragments (raw fp32 bits; mma truncates)
    unsigned aF[8][4];
    #pragma unroll
    for (int ks = 0; ks < 8; ks++) {
        const float* ap = &qS[gid * 68 + ks * 8 + ti];
        aF[ks][0] = __float_as_uint(ap[0]);
        aF[ks][1] = __float_as_uint(ap[8 * 68]);
        aF[ks][2] = __float_as_uint(ap[4]);
        aF[ks][3] = __float_as_uint(ap[8 * 68 + 4]);
    }

    float cO[4] = {0.f, 0.f, 0.f, 0.f};
    int r0 = gid, r1 = gid + 8;
    int cq0 = cbase + r0, cq1 = cbase + r1;

    for (int kt = ktlo; kt <= kthi; kt++) {
        __syncthreads();   // prior tile's P/K/V consumers done
        // stage K and V raw
        #pragma unroll
        for (int p = 0; p < 4; p++) {
            int s = tid + p * 256;
            int r = s >> 4, c4 = (s & 15) * 4;
            int j = j0 + kt * 64 + r;
            bool inr = (j >= 0) && (j < S_);
            const float* srcK = &k[((size_t)(b * S_ + (inr ? j : 0))) * D_ + h * DH_ + c4];
            const float* srcV = &v[((size_t)(b * S_ + (inr ? j : 0))) * D_ + h * DH_ + c4];
            cp_async16z((unsigned)__cvta_generic_to_shared(&Ks[r * 68 + c4]), srcK, inr ? 16 : 0);
            cp_async16z((unsigned)__cvta_generic_to_shared(&Vs[r * 72 + c4]), srcV, inr ? 16 : 0);
        }
        if (tid < 64) {
            int j = j0 + kt * 64 + tid;
            mv[tid] = (j > 0 && j < S_ && mask[b * S_ + j] > 0) ? 1.0f : 0.0f;
        }
        asm volatile("cp.async.commit_group;\n");
        asm volatile("cp.async.wait_group 0;\n");
        __syncthreads();

        // score mma: warp w covers keys n0..n0+7, all 16 rows
        float cS[4] = {0.f, 0.f, 0.f, 0.f};
        #pragma unroll
        for (int ks = 0; ks < 8; ks++) {
            unsigned bb[2];
            bb[0] = __float_as_uint(Ks[(n0 + gid) * 68 + ks * 8 + ti]);
            bb[1] = __float_as_uint(Ks[(n0 + gid) * 68 + ks * 8 + ti + 4]);
            mma_tf32(cS, aF[ks], bb);
        }

        int kk0 = kt * 64 + n0 + 2 * ti;
        float valid0 = mv[n0 + 2 * ti], valid1 = mv[n0 + 2 * ti + 1];
        bool ok00 = (valid0 > 0.5f) && (kk0 >= cq0) && (kk0 <= cq0 + 2 * C_);
        bool ok01 = (valid1 > 0.5f) && (kk0 + 1 >= cq0) && (kk0 + 1 <= cq0 + 2 * C_);
        bool ok10 = (valid0 > 0.5f) && (kk0 >= cq1) && (kk0 <= cq1 + 2 * C_);
        bool ok11 = (valid1 > 0.5f) && (kk0 + 1 >= cq1) && (kk0 + 1 <= cq1 + 2 * C_);
        *(float2*)&P[r0 * 68 + n0 + 2 * ti] =
            make_float2(ok00 ? cS[0] : NEGV, ok01 ? cS[1] : NEGV);
        *(float2*)&P[r1 * 68 + n0 + 2 * ti] =
            make_float2(ok10 ? cS[2] : NEGV, ok11 ? cS[3] : NEGV);
        __syncthreads();

        // online softmax update: warp w owns rows 2w, 2w+1
        #pragma unroll
        for (int rr = 0; rr < 2; rr++) {
            int qi = 2 * w + rr;
            float2 pv = *(float2*)&P[qi * 68 + lane * 2];
            float tm = warp_max(fmaxf(pv.x, pv.y));
            float mo = mrun[qi];
            float mn = fmaxf(mo, tm);
            float e0 = __expf(pv.x - mn);
            float e1 = __expf(pv.y - mn);
            float se = warp_sum(e0 + e1);
            if (lane == 0) {
                float rf = __expf(mo - mn);
                srun[qi] = srun[qi] * rf + se;
                mrun[qi] = mn;
                rsc[qi]  = rf;
            }
            *(float2*)&P[qi * 68 + lane * 2] = make_float2(e0, e1);
        }
        __syncthreads();

        // rescale accumulator + PV mma
        float rf0 = rsc[r0], rf1 = rsc[r1];
        cO[0] *= rf0; cO[1] *= rf0; cO[2] *= rf1; cO[3] *= rf1;
        #pragma unroll
        for (int ks = 0; ks < 8; ks++) {
            unsigned bb[2];
            bb[0] = __float_as_uint(Vs[(ks * 8 + ti) * 72 + n0 + gid]);
            bb[1] = __float_as_uint(Vs[(ks * 8 + ti + 4) * 72 + n0 + gid]);
            unsigned aa[4];
            const unsigned* pp = &Pu[gid * 68 + ks * 8 + ti];
            aa[0] = pp[0];
            aa[1] = pp[8 * 68];
            aa[2] = pp[4];
            aa[3] = pp[8 * 68 + 4];
            mma_tf32(cO, aa, bb);
        }
    }

    // final: fold in global token, normalize, write
    {
        const float* v0p = v + ((size_t)(b * S_)) * D_ + h * DH_;
        int d0 = n0 + 2 * ti;
        float gv0 = v0p[d0], gv1 = v0p[d0 + 1];

        float m0 = mrun[r0], s0 = srun[r0], g0 = gsc[r0];
        float mu0 = fmaxf(m0, g0);
        float rf0 = __expf(m0 - mu0), pg0 = __expf(g0 - mu0);
        float iv0 = 1.0f / (s0 * rf0 + pg0);

        float m1 = mrun[r1], s1 = srun[r1], g1 = gsc[r1];
        float mu1 = fmaxf(m1, g1);
        float rf1 = __expf(m1 - mu1), pg1 = __expf(g1 - mu1);
        float iv1 = 1.0f / (s1 * rf1 + pg1);

        float2 o0 = make_float2((cO[0] * rf0 + pg0 * gv0) * iv0,
                                (cO[1] * rf0 + pg0 * gv1) * iv0);
        float2 o1 = make_float2((cO[2] * rf1 + pg1 * gv0) * iv1,
                                (cO[3] * rf1 + pg1 * gv1) * iv1);
        *(float2*)&ctx[((size_t)(b * S_ + qbase + r0)) * D_ + h * DH_ + d0] = o0;
        *(float2*)&ctx[((size_t)(b * S_ + qbase + r1)) * D_ + h * DH_ + d0] = o1;
    }
}

// ---------------- global-row attention, split-KV ----------------
__global__ __launch_bounds__(128) void gattn_part_kernel(
        const float* __restrict__ q,
        const float* __restrict__ k,
        const float* __restrict__ v,
        const int* __restrict__ mask,
        float* __restrict__ part) {
    __shared__ float qs[64];
    __shared__ float red[32];
    __shared__ float ps[GCK];
    int h = blockIdx.x, b = blockIdx.y, ch = blockIdx.z;
    int tid = threadIdx.x;
    const float* qp = q + ((size_t)(b * S_)) * D_ + h * DH_;
    if (tid < 16) ((float4*)qs)[tid] = ((const float4*)qp)[tid];
    __syncthreads();

    int j = ch * GCK + tid;
    float s = NEGV;
    if (mask[b * S_ + j] > 0) {
        const float4* kp = (const float4*)(k + ((size_t)(b * S_ + j)) * D_ + h * DH_);
        float acc = 0.0f;
        #pragma unroll
        for (int d4 = 0; d4 < 16; d4++) {
            float4 kv = kp[d4];
            float4 qv = ((const float4*)qs)[d4];
            acc += kv.x * qv.x + kv.y * qv.y + kv.z * qv.z + kv.w * qv.w;
        }
        s = acc;
    }
    float m = block_max(s, red);
    float e = __expf(s - m);
    float ssum = block_sum(e, red);
    ps[tid] = e;
    __syncthreads();

    float* op = part + ((size_t)(b * H_ + h) * GNS + ch) * 66;
    if (tid < 64) {
        float acc = 0.0f;
        const float* vp = v + ((size_t)(b * S_ + ch * GCK)) * D_ + h * DH_ + tid;
        #pragma unroll 4
        for (int kk = 0; kk < GCK; kk++)
            acc = fmaf(ps[kk], vp[(size_t)kk * D_], acc);
        op[tid] = acc;
    } else if (tid == 64) {
        op[64] = m;
        op[65] = ssum;
    }
}

__global__ __launch_bounds__(64) void gattn_comb_kernel(
        const float* __restrict__ part,
        float* __restrict__ ctx) {
    int h = blockIdx.x, b = blockIdx.y;
    int tid = threadIdx.x;
    const float* pp = part + ((size_t)(b * H_ + h) * GNS) * 66;
    float M = -INFINITY;
    #pragma unroll
    for (int i = 0; i < GNS; i++) M = fmaxf(M, pp[i * 66 + 64]);
    float S = 0.0f, acc = 0.0f;
    #pragma unroll
    for (int i = 0; i < GNS; i++) {
        float wgt = __expf(pp[i * 66 + 64] - M);
        S += pp[i * 66 + 65] * wgt;
        acc += pp[i * 66 + tid] * wgt;
    }
    ctx[((size_t)(b * S_)) * D_ + h * DH_ + tid] = acc / S;
}

// ---------------- classifier head ----------------
__global__ void cls_kernel(const float* __restrict__ h,
                           const float* __restrict__ W,
                           const float* __restrict__ bias,
                           float* __restrict__ out) {
    int w = threadIdx.x >> 5, lane = threadIdx.x & 31;
    if (w < B_ * 3) {
        int b = w / 3, c = w % 3;
        float acc = 0.0f;
        for (int kx = lane; kx < D_; kx += 32)
            acc += h[((size_t)(b * S_)) * D_ + kx] * W[kx * 3 + c];
        acc = warp_sum(acc);
        if (lane == 0) out[b * 3 + c] = acc + bias[c];
    }
}

// ---------------- launch ----------------
extern "C" void kernel_launch(void* const* d_in, const int* in_sizes, int n_in,
                              void* d_out, int out_size) {
    const int*   ids      = (const int*)d_in[0];
    const int*   mask     = (const int*)d_in[1];
    const float* emb_tok  = (const float*)d_in[2];
    const float* emb_pos  = (const float*)d_in[3];
    const float* emb_ln_g = (const float*)d_in[4];
    const float* emb_ln_b = (const float*)d_in[5];
    const float* Wq = (const float*)d_in[6];
    const float* bq = (const float*)d_in[7];
    const float* Wk = (const float*)d_in[8];
    const float* bk = (const float*)d_in[9];
    const float* Wv = (const float*)d_in[10];
    const float* bv = (const float*)d_in[11];
    const float* Wo = (const float*)d_in[12];
    const float* bo = (const float*)d_in[13];
    const float* ln1_g = (const float*)d_in[14];
    const float* ln1_b = (const float*)d_in[15];
    const float* W1 = (const float*)d_in[16];
    const float* b1 = (const float*)d_in[17];
    const float* W2 = (const float*)d_in[18];
    const float* b2 = (const float*)d_in[19];
    const float* ln2_g = (const float*)d_in[20];
    const float* ln2_b = (const float*)d_in[21];
    const float* clsW = (const float*)d_in[22];
    const float* clsb = (const float*)d_in[23];

    float *h, *q, *k, *v, *ctx, *t, *f, *gp;
    cudaGetSymbolAddress((void**)&h,   g_h);
    cudaGetSymbolAddress((void**)&q,   g_q);
    cudaGetSymbolAddress((void**)&k,   g_k);
    cudaGetSymbolAddress((void**)&v,   g_v);
    cudaGetSymbolAddress((void**)&ctx, g_ctx);
    cudaGetSymbolAddress((void**)&t,   g_t);
    cudaGetSymbolAddress((void**)&f,   g_f);
    cudaGetSymbolAddress((void**)&gp,  g_gp);

    embed_ln_kernel<<<M_, 256>>>(ids, emb_tok, emb_pos, emb_ln_g, emb_ln_b, h);

    for (int l = 0; l < L_; l++) {
        const float* Wql = Wq + (size_t)l * D_ * D_;
        const float* Wkl = Wk + (size_t)l * D_ * D_;
        const float* Wvl = Wv + (size_t)l * D_ * D_;
        const float* Wol = Wo + (size_t)l * D_ * D_;
        const float* W1l = W1 + (size_t)l * D_ * F_;
        const float* W2l = W2 + (size_t)l * F_ * D_;

        dim3 gQKV(D_ / TBN, M_ / TBM, 3);
        dim3 gD(D_ / TBN, M_ / TBM, 1);
        dim3 gF(F_ / TBN, M_ / TBM, 1);

        gemm_tf32_kernel<<<gQKV, 256>>>(h,
            Wql, Wkl, Wvl,
            bq + l * D_, bk + l * D_, bv + l * D_,
            q, k, v,
            M_, D_, D_, 0, 0.125f, 1.0f, 1.0f);

        gattn_part_kernel<<<dim3(H_, B_, GNS), 128>>>(q, k, v, mask, gp);
        sw_attn_kernel<<<dim3(S_ / 16, H_, B_), 256, AT_SMEM>>>(q, k, v, mask, ctx);
        gattn_comb_kernel<<<dim3(H_, B_), 64>>>(gp, ctx);

        gemm_tf32_kernel<<<gD, 256>>>(ctx,
            Wol, Wol, Wol, bo + l * D_, bo + l * D_, bo + l * D_,
            t, t, t, M_, D_, D_, 0, 1.0f, 1.0f, 1.0f);
        add_ln_kernel<<<M_, 256>>>(h, t, ln1_g + l * D_, ln1_b + l * D_, h);

        gemm_tf32_kernel<<<gF, 256>>>(h,
            W1l, W1l, W1l, b1 + l * F_, b1 + l * F_, b1 + l * F_,
            f, f, f, M_, F_, D_, 1, 1.0f, 1.0f, 1.0f);
        gemm_tf32_kernel<<<gD, 256>>>(f,
            W2l, W2l, W2l, b2 + l * D_, b2 + l * D_, b2 + l * D_,
            t, t, t, M_, D_, F_, 0, 1.0f, 1.0f, 1.0f);
        add_ln_kernel<<<M_, 256>>>(h, t, ln2_g + l * D_, ln2_b + l * D_, h);
    }

    cls_kernel<<<1, 256>>>(h, clsW, clsb, (float*)d_out);
}